// round 1
// baseline (speedup 1.0000x reference)
#include <cuda_runtime.h>
#include <math.h>

// Problem constants
#define Bn 4
#define Tn 2048
#define Dn 1024
#define Hn 16
#define HDn 64
#define QKV_STRIDE (Bn * Hn * Tn * HDn)   // 8388608 floats per q/k/v

// Scratch (device globals; no cudaMalloc allowed)
__device__ float g_qkv[3ull * QKV_STRIDE];          // [3][B][H][T][HD]
__device__ float g_attn[(size_t)Bn * Tn * Dn];      // [B][T][D] (H,HD flattened)

// ---------------------------------------------------------------------------
// Generic 128x128x8 fp32 SGEMM, 256 threads, 8x8 micro-tile per thread.
// MODE 0: C = x @ Wqkv, scatter into g_qkv with (3,H,HD) column decode.
// MODE 1: C = g_attn @ Wout, plain write to Cout.
// ---------------------------------------------------------------------------
template<int MODE>
__global__ __launch_bounds__(256)
void sgemm_kernel(const float* __restrict__ Ain, const float* __restrict__ W,
                  float* __restrict__ Cout, int N)
{
    __shared__ float As[8][128];   // transposed A tile: As[k][m]
    __shared__ float Bs[8][128];   // B tile: Bs[k][n]

    const float* A = (MODE == 1) ? g_attn : Ain;
    const int K = Dn;
    const int bm = blockIdx.y * 128;
    const int bn = blockIdx.x * 128;
    const int tid = threadIdx.x;
    const int tx = tid & 15, ty = tid >> 4;
    const int ar = tid >> 1, ac4 = (tid & 1) * 4;   // A load: row ar, 4 cols
    const int bk = tid >> 5, bn4 = (tid & 31) * 4;  // B load: row bk, 4 cols

    float acc[8][8];
#pragma unroll
    for (int i = 0; i < 8; i++)
#pragma unroll
        for (int j = 0; j < 8; j++) acc[i][j] = 0.f;

    for (int k0 = 0; k0 < K; k0 += 8) {
        float4 av = *(const float4*)(A + (size_t)(bm + ar) * K + k0 + ac4);
        float4 bv = *(const float4*)(W + (size_t)(k0 + bk) * N + bn + bn4);
        __syncthreads();
        As[ac4 + 0][ar] = av.x;
        As[ac4 + 1][ar] = av.y;
        As[ac4 + 2][ar] = av.z;
        As[ac4 + 3][ar] = av.w;
        *(float4*)&Bs[bk][bn4] = bv;
        __syncthreads();
#pragma unroll
        for (int k = 0; k < 8; k++) {
            float ra[8], rb[8];
            *(float4*)&ra[0] = *(const float4*)&As[k][ty * 4];
            *(float4*)&ra[4] = *(const float4*)&As[k][64 + ty * 4];
            *(float4*)&rb[0] = *(const float4*)&Bs[k][tx * 4];
            *(float4*)&rb[4] = *(const float4*)&Bs[k][64 + tx * 4];
#pragma unroll
            for (int i = 0; i < 8; i++)
#pragma unroll
                for (int j = 0; j < 8; j++)
                    acc[i][j] += ra[i] * rb[j];
        }
    }

#pragma unroll
    for (int i = 0; i < 8; i++) {
        int row = bm + ((i < 4) ? (ty * 4 + i) : (64 + ty * 4 + (i - 4)));
#pragma unroll
        for (int j = 0; j < 8; j++) {
            int col = bn + ((j < 4) ? (tx * 4 + j) : (64 + tx * 4 + (j - 4)));
            if (MODE == 0) {
                // col = s*1024 + h*64 + d ; row = b*2048 + t
                int s = col >> 10;
                int rem = col & 1023;
                int h = rem >> 6, d = rem & 63;
                int b = row >> 11, t = row & 2047;
                g_qkv[(size_t)s * QKV_STRIDE +
                      (((size_t)(b * Hn + h) * Tn + t) << 6) + d] = acc[i][j];
            } else {
                Cout[(size_t)row * N + col] = acc[i][j];
            }
        }
    }
}

// ---------------------------------------------------------------------------
// Flash-style attention. One block = 64 query rows of one (b,h).
// 256 threads, 4x4 register micro-tiles for both QK^T and PV.
// Sorted position ids -> early-exit over kv blocks when pos[j0] > max(pos_q).
// ---------------------------------------------------------------------------
#define ATTN_LD 68   // padded row stride (floats), 16B-aligned rows

__global__ __launch_bounds__(256)
void attn_kernel(const int* __restrict__ pos)
{
    extern __shared__ float sm[];
    float* Qs = sm;                       // [64][68]  (token, dim)
    float* Ks = Qs + 64 * ATTN_LD;        // [64][68]  (token, dim)
    float* Vt = Ks + 64 * ATTN_LD;        // [64][68]  (dim, token) transposed
    float* Sm = Vt + 64 * ATTN_LD;        // [64][68]  scores -> probs
    int*   posq = (int*)(Sm + 64 * ATTN_LD);
    int*   posk = posq + 64;
    float* mrow = (float*)(posk + 64);
    float* lrow = mrow + 64;
    float* arow = lrow + 64;

    const int bh = blockIdx.y;
    const int b = bh >> 4, h = bh & 15;
    const int i0 = blockIdx.x * 64;
    const int tid = threadIdx.x;
    const int tx = tid & 15, ty = tid >> 4;

    const float* Qg = g_qkv + ((size_t)(b * Hn + h) * Tn + i0) * HDn;
    const float* Kg = g_qkv + (size_t)QKV_STRIDE + (size_t)(b * Hn + h) * Tn * HDn;
    const float* Vg = g_qkv + 2ull * QKV_STRIDE + (size_t)(b * Hn + h) * Tn * HDn;

    // Load Q tile (64x64) -> Qs
#pragma unroll
    for (int r = 0; r < 4; r++) {
        int idx = r * 256 + tid;           // 0..1023
        int i = idx >> 4, d4 = (idx & 15) * 4;
        *(float4*)&Qs[i * ATTN_LD + d4] = *(const float4*)(Qg + i * 64 + d4);
    }
    if (tid < 64) {
        posq[tid] = pos[b * Tn + i0 + tid];
        mrow[tid] = -3e38f;
        lrow[tid] = 0.f;
    }
    __syncthreads();

    const int pqmax = posq[63];            // positions are sorted ascending
    int my_pq[4];
#pragma unroll
    for (int ii = 0; ii < 4; ii++) my_pq[ii] = posq[ty + 16 * ii];

    float acc_o[4][4];
#pragma unroll
    for (int i = 0; i < 4; i++)
#pragma unroll
        for (int j = 0; j < 4; j++) acc_o[i][j] = 0.f;

    for (int j0 = 0; j0 < Tn; j0 += 64) {
        if (pos[b * Tn + j0] > pqmax) break;   // whole kv block is in the future

        // Load K (row-major) and V (transposed) tiles
#pragma unroll
        for (int r = 0; r < 4; r++) {
            int idx = r * 256 + tid;
            int j = idx >> 4, d4 = (idx & 15) * 4;
            *(float4*)&Ks[j * ATTN_LD + d4] =
                *(const float4*)(Kg + (size_t)(j0 + j) * 64 + d4);
            float4 v = *(const float4*)(Vg + (size_t)(j0 + j) * 64 + d4);
            Vt[(d4 + 0) * ATTN_LD + j] = v.x;
            Vt[(d4 + 1) * ATTN_LD + j] = v.y;
            Vt[(d4 + 2) * ATTN_LD + j] = v.z;
            Vt[(d4 + 3) * ATTN_LD + j] = v.w;
        }
        if (tid < 64) posk[tid] = pos[b * Tn + j0 + tid];
        __syncthreads();

        // S = Q K^T  (rows = ty+16*ii, cols = tx+16*jj)
        float acc_s[4][4];
#pragma unroll
        for (int i = 0; i < 4; i++)
#pragma unroll
            for (int j = 0; j < 4; j++) acc_s[i][j] = 0.f;

#pragma unroll
        for (int d0 = 0; d0 < 64; d0 += 4) {
            float4 ra[4], rb[4];
#pragma unroll
            for (int ii = 0; ii < 4; ii++)
                ra[ii] = *(const float4*)&Qs[(ty + 16 * ii) * ATTN_LD + d0];
#pragma unroll
            for (int jj = 0; jj < 4; jj++)
                rb[jj] = *(const float4*)&Ks[(tx + 16 * jj) * ATTN_LD + d0];
#pragma unroll
            for (int ii = 0; ii < 4; ii++)
#pragma unroll
                for (int jj = 0; jj < 4; jj++) {
                    acc_s[ii][jj] += ra[ii].x * rb[jj].x;
                    acc_s[ii][jj] += ra[ii].y * rb[jj].y;
                    acc_s[ii][jj] += ra[ii].z * rb[jj].z;
                    acc_s[ii][jj] += ra[ii].w * rb[jj].w;
                }
        }

        // scale + position mask, write to Sm
#pragma unroll
        for (int jj = 0; jj < 4; jj++) {
            int pk = posk[tx + 16 * jj];
#pragma unroll
            for (int ii = 0; ii < 4; ii++) {
                float s = acc_s[ii][jj] * 0.125f;
                if (my_pq[ii] < pk) s = -1e30f;
                Sm[(ty + 16 * ii) * ATTN_LD + tx + 16 * jj] = s;
            }
        }
        __syncthreads();

        // Online softmax: 4 threads per row, 16 cols each
        {
            int row = tid >> 2, part = tid & 3;
            float* srow = &Sm[row * ATTN_LD + part * 16];
            float mx = -3e38f;
#pragma unroll
            for (int c = 0; c < 16; c++) mx = fmaxf(mx, srow[c]);
            mx = fmaxf(mx, __shfl_xor_sync(0xffffffffu, mx, 1));
            mx = fmaxf(mx, __shfl_xor_sync(0xffffffffu, mx, 2));
            float mold = mrow[row];
            float mnew = fmaxf(mold, mx);
            float ssum = 0.f;
#pragma unroll
            for (int c = 0; c < 16; c++) {
                float p = __expf(srow[c] - mnew);
                srow[c] = p;
                ssum += p;
            }
            ssum += __shfl_xor_sync(0xffffffffu, ssum, 1);
            ssum += __shfl_xor_sync(0xffffffffu, ssum, 2);
            if (part == 0) {
                float al = __expf(mold - mnew);
                arow[row] = al;
                mrow[row] = mnew;
                lrow[row] = lrow[row] * al + ssum;
            }
        }
        __syncthreads();

        // Rescale accumulators, then O += P @ V  (cols = tx+16*dc)
        float al[4];
#pragma unroll
        for (int ii = 0; ii < 4; ii++) al[ii] = arow[ty + 16 * ii];
#pragma unroll
        for (int ii = 0; ii < 4; ii++)
#pragma unroll
            for (int dc = 0; dc < 4; dc++) acc_o[ii][dc] *= al[ii];

#pragma unroll
        for (int j4 = 0; j4 < 64; j4 += 4) {
            float4 rp[4], rv[4];
#pragma unroll
            for (int ii = 0; ii < 4; ii++)
                rp[ii] = *(const float4*)&Sm[(ty + 16 * ii) * ATTN_LD + j4];
#pragma unroll
            for (int dc = 0; dc < 4; dc++)
                rv[dc] = *(const float4*)&Vt[(tx + 16 * dc) * ATTN_LD + j4];
#pragma unroll
            for (int ii = 0; ii < 4; ii++)
#pragma unroll
                for (int dc = 0; dc < 4; dc++) {
                    acc_o[ii][dc] += rp[ii].x * rv[dc].x;
                    acc_o[ii][dc] += rp[ii].y * rv[dc].y;
                    acc_o[ii][dc] += rp[ii].z * rv[dc].z;
                    acc_o[ii][dc] += rp[ii].w * rv[dc].w;
                }
        }
        __syncthreads();   // before next iteration overwrites Ks/Vt/Sm
    }

    // Epilogue: normalize and write (B,T,H*HD)
#pragma unroll
    for (int ii = 0; ii < 4; ii++) {
        int i = ty + 16 * ii;
        float inv = 1.f / lrow[i];
        int t = i0 + i;
#pragma unroll
        for (int dc = 0; dc < 4; dc++) {
            int d = tx + 16 * dc;
            g_attn[((size_t)b * Tn + t) * Dn + h * HDn + d] = acc_o[ii][dc] * inv;
        }
    }
}

// ---------------------------------------------------------------------------
extern "C" void kernel_launch(void* const* d_in, const int* in_sizes, int n_in,
                              void* d_out, int out_size)
{
    const float* x   = (const float*)d_in[0];
    const int*   pos = (const int*)d_in[1];
    const float* Wq  = (const float*)d_in[2];
    const float* Wo  = (const float*)d_in[3];
    float* out = (float*)d_out;

    // 1) QKV projection: (8192,1024) @ (1024,3072) -> scattered q/k/v
    dim3 g1((3 * Dn) / 128, (Bn * Tn) / 128);   // (24, 64)
    sgemm_kernel<0><<<g1, 256>>>(x, Wq, nullptr, 3 * Dn);

    // 2) Attention
    const int ATTN_SMEM = (4 * 64 * ATTN_LD) * 4 + 2 * 64 * 4 + 3 * 64 * 4;
    cudaFuncSetAttribute(attn_kernel,
                         cudaFuncAttributeMaxDynamicSharedMemorySize, ATTN_SMEM);
    dim3 g2(Tn / 64, Bn * Hn);                  // (32, 64)
    attn_kernel<<<g2, 256, ATTN_SMEM>>>(pos);

    // 3) Output projection: (8192,1024) @ (1024,1024) -> d_out
    dim3 g3(Dn / 128, (Bn * Tn) / 128);         // (8, 64)
    sgemm_kernel<1><<<g3, 256>>>(nullptr, Wo, out, Dn);
}

// round 3
// speedup vs baseline: 1.6725x; 1.6725x over previous
#include <cuda_runtime.h>
#include <cuda_bf16.h>
#include <math.h>
#include <stdint.h>

// Problem constants
#define Bn 4
#define Tn 2048
#define Dn 1024
#define Hn 16
#define HDn 64
#define QKV_STRIDE (Bn * Hn * Tn * HDn)   // 8388608 floats per q/k/v

// ---------------------------------------------------------------------------
// Device scratch (no cudaMalloc allowed)
// ---------------------------------------------------------------------------
__device__ float g_qkv[3ull * QKV_STRIDE];              // [3][B][H][T][HD] fp32
__device__ float g_attn[(size_t)Bn * Tn * Dn];          // [B][T][D] fp32

// bf16 hi/lo splits (raw u16), all in native (row-major) layout
__device__ unsigned short xa_hi[(size_t)Bn * Tn * Dn];  // [8192][1024]
__device__ unsigned short xa_lo[(size_t)Bn * Tn * Dn];
__device__ unsigned short wq_hi[(size_t)3 * Dn * Dn];   // [1024][3072]  (K-major, native)
__device__ unsigned short wq_lo[(size_t)3 * Dn * Dn];
__device__ unsigned short wo_hi[(size_t)Dn * Dn];       // [1024][1024]  (K-major, native)
__device__ unsigned short wo_lo[(size_t)Dn * Dn];
__device__ unsigned short ga_hi[(size_t)Bn * Tn * Dn];  // attn out split
__device__ unsigned short ga_lo[(size_t)Bn * Tn * Dn];

// ---------------------------------------------------------------------------
// PTX helpers (all non-arch-specific: work on plain sm_103 target)
// ---------------------------------------------------------------------------
__device__ __forceinline__ uint32_t s2u(const void* p) {
    uint32_t a;
    asm("{ .reg .u64 t; cvta.to.shared.u64 t, %1; cvt.u32.u64 %0, t; }"
        : "=r"(a) : "l"(p));
    return a;
}
__device__ __forceinline__ void cpa16(uint32_t d, const void* s) {
    asm volatile("cp.async.cg.shared.global [%0], [%1], 16;"
                 :: "r"(d), "l"(s) : "memory");
}
__device__ __forceinline__ void cpa_commit() {
    asm volatile("cp.async.commit_group;" ::: "memory");
}
template<int N>
__device__ __forceinline__ void cpa_wait() {
    asm volatile("cp.async.wait_group %0;" :: "n"(N) : "memory");
}
__device__ __forceinline__ void ldsm4(uint32_t* r, uint32_t a) {
    asm volatile("ldmatrix.sync.aligned.m8n8.x4.shared.b16 {%0,%1,%2,%3}, [%4];"
        : "=r"(r[0]), "=r"(r[1]), "=r"(r[2]), "=r"(r[3]) : "r"(a));
}
__device__ __forceinline__ void ldsm4t(uint32_t* r, uint32_t a) {
    asm volatile("ldmatrix.sync.aligned.m8n8.x4.trans.shared.b16 {%0,%1,%2,%3}, [%4];"
        : "=r"(r[0]), "=r"(r[1]), "=r"(r[2]), "=r"(r[3]) : "r"(a));
}
__device__ __forceinline__ void mma16816(float* d, const uint32_t* a, const uint32_t* b) {
    asm volatile(
        "mma.sync.aligned.m16n8k16.row.col.f32.bf16.bf16.f32 "
        "{%0,%1,%2,%3}, {%4,%5,%6,%7}, {%8,%9}, {%0,%1,%2,%3};"
        : "+f"(d[0]), "+f"(d[1]), "+f"(d[2]), "+f"(d[3])
        : "r"(a[0]), "r"(a[1]), "r"(a[2]), "r"(a[3]), "r"(b[0]), "r"(b[1]));
}

// Swizzles (byte-offset XOR), chosen so ldmatrix's 8x16B accesses are conflict-free.
// A buffer: [128 rows][32 bf16] -> 64B rows
#define SWA(o) ((o) ^ ((((o) >> 7) & 3) << 4))
// B buffer: [32 rows(k)][128 bf16] -> 256B rows
#define SWB(o) ((o) ^ ((((o) >> 8) & 7) << 4))

// ---------------------------------------------------------------------------
// Split converters: fp32 -> (bf16 hi, bf16 lo)
// ---------------------------------------------------------------------------
__device__ __forceinline__ void split1(float v, unsigned short& h, unsigned short& l) {
    __nv_bfloat16 hb = __float2bfloat16(v);
    float r = v - __bfloat162float(hb);
    __nv_bfloat16 lb = __float2bfloat16(r);
    h = reinterpret_cast<unsigned short&>(hb);
    l = reinterpret_cast<unsigned short&>(lb);
}

__global__ __launch_bounds__(256)
void split_kernel(const float* __restrict__ in, unsigned short* __restrict__ hi,
                  unsigned short* __restrict__ lo, int n4)
{
    int i = blockIdx.x * 256 + threadIdx.x;
    if (i >= n4) return;
    float4 v = ((const float4*)in)[i];
    ushort4 h, l;
    split1(v.x, h.x, l.x);
    split1(v.y, h.y, l.y);
    split1(v.z, h.z, l.z);
    split1(v.w, h.w, l.w);
    ((ushort4*)hi)[i] = h;
    ((ushort4*)lo)[i] = l;
}

// ---------------------------------------------------------------------------
// bf16x3 GEMM via mma.sync: D[8192][NN] = A[8192][1024] @ B[1024][NN]
// 128x128 CTA tile, BK=32, 3-stage cp.async pipeline, 8 warps (4x2),
// warp tile 32x64 (2 m16 x 8 n8 fragments).
// MODE 0: scatter fp32 into g_qkv.  MODE 1: plain write to Cout.
// ---------------------------------------------------------------------------
#define BK 32
#define NKB2 32                 // 1024 / BK
#define STAGES 3
#define ABUF 8192               // 128x32 bf16
#define BBUF 8192               // 32x128 bf16
#define STG_BYTES (2 * ABUF + 2 * BBUF)   // 32768

template<int MODE, int NN>
__global__ __launch_bounds__(256)
void tc_gemm(const unsigned short* __restrict__ Ah, const unsigned short* __restrict__ Al,
             const unsigned short* __restrict__ Bh, const unsigned short* __restrict__ Bl,
             float* __restrict__ Cout)
{
    extern __shared__ __align__(1024) unsigned char gsm[];
    const uint32_t sbase = s2u(gsm);
    const int tid = threadIdx.x;
    const int lane = tid & 31, wid = tid >> 5;
    const int wm = wid & 3, wn = wid >> 2;          // warp grid 4(m) x 2(n)
    const int bm = blockIdx.y * 128, bn = blockIdx.x * 128;

    const unsigned short* Abases[2] = { Ah + (size_t)bm * 1024, Al + (size_t)bm * 1024 };
    const unsigned short* Bbases[2] = { Bh + bn, Bl + bn };

    // per-stage loader: A = 2 x 512 chunks (2/thread), B = 2 x 512 chunks (2/thread)
    auto load_stage = [&](int st, int kb) {
        uint32_t sb = sbase + st * STG_BYTES;
#pragma unroll
        for (int sp = 0; sp < 2; sp++) {
#pragma unroll
            for (int i = 0; i < 2; i++) {
                int id = tid * 2 + i;
                // A: row r (0..127), chunk c (0..3) of 16B
                int r = id >> 2, c = id & 3;
                cpa16(sb + sp * ABUF + SWA(r * 64 + c * 16),
                      Abases[sp] + (size_t)r * 1024 + kb * BK + c * 8);
                // B: row k (0..31), chunk c (0..15) of 16B
                int rk = id >> 4, cc = id & 15;
                cpa16(sb + 2 * ABUF + sp * BBUF + SWB(rk * 256 + cc * 16),
                      Bbases[sp] + (size_t)(kb * BK + rk) * NN + cc * 8);
            }
        }
    };

    float acc[2][8][4];
#pragma unroll
    for (int mt = 0; mt < 2; mt++)
#pragma unroll
        for (int nt = 0; nt < 8; nt++)
#pragma unroll
            for (int q = 0; q < 4; q++) acc[mt][nt][q] = 0.f;

    load_stage(0, 0); cpa_commit();
    load_stage(1, 1); cpa_commit();

    const int a_lr = lane & 15;                  // ldmatrix lane row
    const int a_hk = (lane >> 4) << 4;           // +16B for lanes 16..31

    for (int kb = 0; kb < NKB2; kb++) {
        const int cur = kb % STAGES;
        if (kb >= NKB2 - 2) cpa_wait<0>(); else cpa_wait<1>();
        __syncthreads();

        uint32_t sb = sbase + cur * STG_BYTES;
#pragma unroll
        for (int ks = 0; ks < 2; ks++) {
            // A fragments: [split][mtile][4]
            uint32_t afr[2][2][4];
#pragma unroll
            for (int sp = 0; sp < 2; sp++)
#pragma unroll
                for (int mt = 0; mt < 2; mt++) {
                    int r = wm * 32 + mt * 16 + a_lr;
                    ldsm4(afr[sp][mt], sb + sp * ABUF + SWA(r * 64 + ks * 32 + a_hk));
                }
            // B fragments: [split][ntile][2]
            uint32_t bfr[2][8][2];
#pragma unroll
            for (int sp = 0; sp < 2; sp++)
#pragma unroll
                for (int nt2 = 0; nt2 < 4; nt2++) {
                    int kk = ks * 16 + a_lr;
                    int nb = wn * 128 + nt2 * 32 + a_hk;
                    uint32_t t[4];
                    ldsm4t(t, sb + 2 * ABUF + sp * BBUF + SWB(kk * 256 + nb));
                    bfr[sp][nt2 * 2][0] = t[0]; bfr[sp][nt2 * 2][1] = t[1];
                    bfr[sp][nt2 * 2 + 1][0] = t[2]; bfr[sp][nt2 * 2 + 1][1] = t[3];
                }
            // bf16x3: hi*hi + hi*lo + lo*hi
#pragma unroll
            for (int mt = 0; mt < 2; mt++)
#pragma unroll
                for (int nt = 0; nt < 8; nt++) {
                    mma16816(acc[mt][nt], afr[0][mt], bfr[0][nt]);
                    mma16816(acc[mt][nt], afr[0][mt], bfr[1][nt]);
                    mma16816(acc[mt][nt], afr[1][mt], bfr[0][nt]);
                }
        }
        __syncthreads();
        if (kb + STAGES - 1 < NKB2) {
            load_stage((kb + STAGES - 1) % STAGES, kb + STAGES - 1);
            cpa_commit();
        }
    }

    // Epilogue: fragment layout c0,c1 -> (row gid, col 2tg,2tg+1); c2,c3 -> row gid+8
    const int gid = lane >> 2, tg = lane & 3;
#pragma unroll
    for (int mt = 0; mt < 2; mt++)
#pragma unroll
        for (int nt = 0; nt < 8; nt++) {
            int row0 = bm + wm * 32 + mt * 16 + gid;
            int col = bn + wn * 64 + nt * 8 + tg * 2;
#pragma unroll
            for (int half = 0; half < 2; half++) {
                int row = row0 + half * 8;
                float2 v = make_float2(acc[mt][nt][half * 2], acc[mt][nt][half * 2 + 1]);
                if (MODE == 0) {
                    int s = col >> 10, h = (col >> 6) & 15, d = col & 63;
                    int b = row >> 11, t = row & 2047;
                    *(float2*)&g_qkv[(size_t)s * QKV_STRIDE +
                                     (((size_t)(b * Hn + h) * Tn + t) << 6) + d] = v;
                } else {
                    *(float2*)&Cout[(size_t)row * NN + col] = v;
                }
            }
        }
}

// ---------------------------------------------------------------------------
// Flash-style SIMT attention (unchanged from R1 — known good)
// ---------------------------------------------------------------------------
#define ATTN_LD 68

__global__ __launch_bounds__(256)
void attn_kernel(const int* __restrict__ pos)
{
    extern __shared__ float sm[];
    float* Qs = sm;
    float* Ks = Qs + 64 * ATTN_LD;
    float* Vt = Ks + 64 * ATTN_LD;
    float* Sm = Vt + 64 * ATTN_LD;
    int*   posq = (int*)(Sm + 64 * ATTN_LD);
    int*   posk = posq + 64;
    float* mrow = (float*)(posk + 64);
    float* lrow = mrow + 64;
    float* arow = lrow + 64;

    const int bh = blockIdx.y;
    const int b = bh >> 4, h = bh & 15;
    const int i0 = blockIdx.x * 64;
    const int tid = threadIdx.x;
    const int tx = tid & 15, ty = tid >> 4;

    const float* Qg = g_qkv + ((size_t)(b * Hn + h) * Tn + i0) * HDn;
    const float* Kg = g_qkv + (size_t)QKV_STRIDE + (size_t)(b * Hn + h) * Tn * HDn;
    const float* Vg = g_qkv + 2ull * QKV_STRIDE + (size_t)(b * Hn + h) * Tn * HDn;

#pragma unroll
    for (int r = 0; r < 4; r++) {
        int idx = r * 256 + tid;
        int i = idx >> 4, d4 = (idx & 15) * 4;
        *(float4*)&Qs[i * ATTN_LD + d4] = *(const float4*)(Qg + i * 64 + d4);
    }
    if (tid < 64) {
        posq[tid] = pos[b * Tn + i0 + tid];
        mrow[tid] = -3e38f;
        lrow[tid] = 0.f;
    }
    __syncthreads();

    const int pqmax = posq[63];
    int my_pq[4];
#pragma unroll
    for (int ii = 0; ii < 4; ii++) my_pq[ii] = posq[ty + 16 * ii];

    float acc_o[4][4];
#pragma unroll
    for (int i = 0; i < 4; i++)
#pragma unroll
        for (int j = 0; j < 4; j++) acc_o[i][j] = 0.f;

    for (int j0 = 0; j0 < Tn; j0 += 64) {
        if (pos[b * Tn + j0] > pqmax) break;

#pragma unroll
        for (int r = 0; r < 4; r++) {
            int idx = r * 256 + tid;
            int j = idx >> 4, d4 = (idx & 15) * 4;
            *(float4*)&Ks[j * ATTN_LD + d4] =
                *(const float4*)(Kg + (size_t)(j0 + j) * 64 + d4);
            float4 v = *(const float4*)(Vg + (size_t)(j0 + j) * 64 + d4);
            Vt[(d4 + 0) * ATTN_LD + j] = v.x;
            Vt[(d4 + 1) * ATTN_LD + j] = v.y;
            Vt[(d4 + 2) * ATTN_LD + j] = v.z;
            Vt[(d4 + 3) * ATTN_LD + j] = v.w;
        }
        if (tid < 64) posk[tid] = pos[b * Tn + j0 + tid];
        __syncthreads();

        float acc_s[4][4];
#pragma unroll
        for (int i = 0; i < 4; i++)
#pragma unroll
            for (int j = 0; j < 4; j++) acc_s[i][j] = 0.f;

#pragma unroll
        for (int d0 = 0; d0 < 64; d0 += 4) {
            float4 ra[4], rb[4];
#pragma unroll
            for (int ii = 0; ii < 4; ii++)
                ra[ii] = *(const float4*)&Qs[(ty + 16 * ii) * ATTN_LD + d0];
#pragma unroll
            for (int jj = 0; jj < 4; jj++)
                rb[jj] = *(const float4*)&Ks[(tx + 16 * jj) * ATTN_LD + d0];
#pragma unroll
            for (int ii = 0; ii < 4; ii++)
#pragma unroll
                for (int jj = 0; jj < 4; jj++) {
                    acc_s[ii][jj] += ra[ii].x * rb[jj].x;
                    acc_s[ii][jj] += ra[ii].y * rb[jj].y;
                    acc_s[ii][jj] += ra[ii].z * rb[jj].z;
                    acc_s[ii][jj] += ra[ii].w * rb[jj].w;
                }
        }

#pragma unroll
        for (int jj = 0; jj < 4; jj++) {
            int pk = posk[tx + 16 * jj];
#pragma unroll
            for (int ii = 0; ii < 4; ii++) {
                float s = acc_s[ii][jj] * 0.125f;
                if (my_pq[ii] < pk) s = -1e30f;
                Sm[(ty + 16 * ii) * ATTN_LD + tx + 16 * jj] = s;
            }
        }
        __syncthreads();

        {
            int row = tid >> 2, part = tid & 3;
            float* srow = &Sm[row * ATTN_LD + part * 16];
            float mx = -3e38f;
#pragma unroll
            for (int c = 0; c < 16; c++) mx = fmaxf(mx, srow[c]);
            mx = fmaxf(mx, __shfl_xor_sync(0xffffffffu, mx, 1));
            mx = fmaxf(mx, __shfl_xor_sync(0xffffffffu, mx, 2));
            float mold = mrow[row];
            float mnew = fmaxf(mold, mx);
            float ssum = 0.f;
#pragma unroll
            for (int c = 0; c < 16; c++) {
                float p = __expf(srow[c] - mnew);
                srow[c] = p;
                ssum += p;
            }
            ssum += __shfl_xor_sync(0xffffffffu, ssum, 1);
            ssum += __shfl_xor_sync(0xffffffffu, ssum, 2);
            if (part == 0) {
                float al = __expf(mold - mnew);
                arow[row] = al;
                mrow[row] = mnew;
                lrow[row] = lrow[row] * al + ssum;
            }
        }
        __syncthreads();

        float al[4];
#pragma unroll
        for (int ii = 0; ii < 4; ii++) al[ii] = arow[ty + 16 * ii];
#pragma unroll
        for (int ii = 0; ii < 4; ii++)
#pragma unroll
            for (int dc = 0; dc < 4; dc++) acc_o[ii][dc] *= al[ii];

#pragma unroll
        for (int j4 = 0; j4 < 64; j4 += 4) {
            float4 rp[4], rv[4];
#pragma unroll
            for (int ii = 0; ii < 4; ii++)
                rp[ii] = *(const float4*)&Sm[(ty + 16 * ii) * ATTN_LD + j4];
#pragma unroll
            for (int dc = 0; dc < 4; dc++)
                rv[dc] = *(const float4*)&Vt[(tx + 16 * dc) * ATTN_LD + j4];
#pragma unroll
            for (int ii = 0; ii < 4; ii++)
#pragma unroll
                for (int dc = 0; dc < 4; dc++) {
                    acc_o[ii][dc] += rp[ii].x * rv[dc].x;
                    acc_o[ii][dc] += rp[ii].y * rv[dc].y;
                    acc_o[ii][dc] += rp[ii].z * rv[dc].z;
                    acc_o[ii][dc] += rp[ii].w * rv[dc].w;
                }
        }
        __syncthreads();
    }

#pragma unroll
    for (int ii = 0; ii < 4; ii++) {
        int i = ty + 16 * ii;
        float inv = 1.f / lrow[i];
        int t = i0 + i;
#pragma unroll
        for (int dc = 0; dc < 4; dc++) {
            int d = tx + 16 * dc;
            g_attn[((size_t)b * Tn + t) * Dn + h * HDn + d] = acc_o[ii][dc] * inv;
        }
    }
}

// ---------------------------------------------------------------------------
extern "C" void kernel_launch(void* const* d_in, const int* in_sizes, int n_in,
                              void* d_out, int out_size)
{
    const float* x   = (const float*)d_in[0];
    const int*   pos = (const int*)d_in[1];
    const float* Wq  = (const float*)d_in[2];
    const float* Wo  = (const float*)d_in[3];
    float* out = (float*)d_out;

    unsigned short *p_xh, *p_xl, *p_wqh, *p_wql, *p_woh, *p_wol, *p_gah, *p_gal;
    float *p_gattn;
    cudaGetSymbolAddress((void**)&p_xh,  xa_hi);
    cudaGetSymbolAddress((void**)&p_xl,  xa_lo);
    cudaGetSymbolAddress((void**)&p_wqh, wq_hi);
    cudaGetSymbolAddress((void**)&p_wql, wq_lo);
    cudaGetSymbolAddress((void**)&p_woh, wo_hi);
    cudaGetSymbolAddress((void**)&p_wol, wo_lo);
    cudaGetSymbolAddress((void**)&p_gah, ga_hi);
    cudaGetSymbolAddress((void**)&p_gal, ga_lo);
    cudaGetSymbolAddress((void**)&p_gattn, g_attn);

    const int GEMM_SMEM = STAGES * STG_BYTES;   // 98304

    // 0) elementwise bf16 hi/lo splits (weights stay K-major, no transpose)
    int n4x = (Bn * Tn * Dn) / 4;
    split_kernel<<<(n4x + 255) / 256, 256>>>(x, p_xh, p_xl, n4x);
    int n4wq = (3 * Dn * Dn) / 4;
    split_kernel<<<(n4wq + 255) / 256, 256>>>(Wq, p_wqh, p_wql, n4wq);
    int n4wo = (Dn * Dn) / 4;
    split_kernel<<<(n4wo + 255) / 256, 256>>>(Wo, p_woh, p_wol, n4wo);

    // 1) QKV projection (mma.sync bf16x3) -> g_qkv
    cudaFuncSetAttribute(tc_gemm<0, 3072>,
                         cudaFuncAttributeMaxDynamicSharedMemorySize, GEMM_SMEM);
    tc_gemm<0, 3072><<<dim3(24, 64), 256, GEMM_SMEM>>>(p_xh, p_xl, p_wqh, p_wql, nullptr);

    // 2) attention (SIMT)
    const int ATTN_SMEM = (4 * 64 * ATTN_LD) * 4 + 2 * 64 * 4 + 3 * 64 * 4;
    cudaFuncSetAttribute(attn_kernel,
                         cudaFuncAttributeMaxDynamicSharedMemorySize, ATTN_SMEM);
    attn_kernel<<<dim3(Tn / 64, Bn * Hn), 256, ATTN_SMEM>>>(pos);

    // 2b) split attention output
    split_kernel<<<(n4x + 255) / 256, 256>>>(p_gattn, p_gah, p_gal, n4x);

    // 3) output projection (mma.sync bf16x3) -> d_out
    cudaFuncSetAttribute(tc_gemm<1, 1024>,
                         cudaFuncAttributeMaxDynamicSharedMemorySize, GEMM_SMEM);
    tc_gemm<1, 1024><<<dim3(8, 64), 256, GEMM_SMEM>>>(p_gah, p_gal, p_woh, p_wol, out);
}

// round 4
// speedup vs baseline: 3.1814x; 1.9022x over previous
#include <cuda_runtime.h>
#include <cuda_bf16.h>
#include <math.h>
#include <stdint.h>

// Problem constants
#define Bn 4
#define Tn 2048
#define Dn 1024
#define Hn 16
#define HDn 64
#define QKV_STRIDE (Bn * Hn * Tn * HDn)   // 8388608 elems per q/k/v

// ---------------------------------------------------------------------------
// Device scratch (no cudaMalloc allowed)
// ---------------------------------------------------------------------------
__device__ unsigned short qkvh[3ull * QKV_STRIDE];      // [3][B][H][T][HD] bf16 hi
__device__ unsigned short qkvl[3ull * QKV_STRIDE];      // bf16 lo
__device__ unsigned short xa_hi[(size_t)Bn * Tn * Dn];  // x split [8192][1024]
__device__ unsigned short xa_lo[(size_t)Bn * Tn * Dn];
__device__ unsigned short wq_hi[(size_t)3 * Dn * Dn];   // Wqkv split (native K-major)
__device__ unsigned short wq_lo[(size_t)3 * Dn * Dn];
__device__ unsigned short wo_hi[(size_t)Dn * Dn];       // Wout split
__device__ unsigned short wo_lo[(size_t)Dn * Dn];
__device__ unsigned short ga_hi[(size_t)Bn * Tn * Dn];  // attention out split
__device__ unsigned short ga_lo[(size_t)Bn * Tn * Dn];

// ---------------------------------------------------------------------------
// PTX helpers (non-arch-suffixed; valid on plain sm_103 target)
// ---------------------------------------------------------------------------
__device__ __forceinline__ uint32_t s2u(const void* p) {
    uint32_t a;
    asm("{ .reg .u64 t; cvta.to.shared.u64 t, %1; cvt.u32.u64 %0, t; }"
        : "=r"(a) : "l"(p));
    return a;
}
__device__ __forceinline__ void cpa16(uint32_t d, const void* s) {
    asm volatile("cp.async.cg.shared.global [%0], [%1], 16;"
                 :: "r"(d), "l"(s) : "memory");
}
__device__ __forceinline__ void cpa_commit() {
    asm volatile("cp.async.commit_group;" ::: "memory");
}
template<int N>
__device__ __forceinline__ void cpa_wait() {
    asm volatile("cp.async.wait_group %0;" :: "n"(N) : "memory");
}
__device__ __forceinline__ void ldsm4(uint32_t* r, uint32_t a) {
    asm volatile("ldmatrix.sync.aligned.m8n8.x4.shared.b16 {%0,%1,%2,%3}, [%4];"
        : "=r"(r[0]), "=r"(r[1]), "=r"(r[2]), "=r"(r[3]) : "r"(a));
}
__device__ __forceinline__ void ldsm4t(uint32_t* r, uint32_t a) {
    asm volatile("ldmatrix.sync.aligned.m8n8.x4.trans.shared.b16 {%0,%1,%2,%3}, [%4];"
        : "=r"(r[0]), "=r"(r[1]), "=r"(r[2]), "=r"(r[3]) : "r"(a));
}
__device__ __forceinline__ void mma16816(float* d, const uint32_t* a, const uint32_t* b) {
    asm volatile(
        "mma.sync.aligned.m16n8k16.row.col.f32.bf16.bf16.f32 "
        "{%0,%1,%2,%3}, {%4,%5,%6,%7}, {%8,%9}, {%0,%1,%2,%3};"
        : "+f"(d[0]), "+f"(d[1]), "+f"(d[2]), "+f"(d[3])
        : "r"(a[0]), "r"(a[1]), "r"(a[2]), "r"(a[3]), "r"(b[0]), "r"(b[1]));
}
// pack two f32 into bf16x2: low half = lo, high half = hi
__device__ __forceinline__ uint32_t pack_bf2(float lo, float hi) {
    uint32_t d;
    asm("cvt.rn.bf16x2.f32 %0, %1, %2;" : "=r"(d) : "f"(hi), "f"(lo));
    return d;
}

// Swizzles
#define SWA(o) ((o) ^ ((((o) >> 7) & 3) << 4))   // 64B rows (GEMM A buf)
#define SWB(o) ((o) ^ ((((o) >> 8) & 7) << 4))   // 256B rows (GEMM B buf)
#define SW128(o) ((o) ^ ((((o) >> 7) & 7) << 4)) // 128B rows (attention)

// ---------------------------------------------------------------------------
// fp32 -> (bf16 hi, bf16 lo)
// ---------------------------------------------------------------------------
__device__ __forceinline__ void split1(float v, unsigned short& h, unsigned short& l) {
    __nv_bfloat16 hb = __float2bfloat16(v);
    float r = v - __bfloat162float(hb);
    __nv_bfloat16 lb = __float2bfloat16(r);
    h = reinterpret_cast<unsigned short&>(hb);
    l = reinterpret_cast<unsigned short&>(lb);
}

__global__ __launch_bounds__(256)
void split_kernel(const float* __restrict__ in, unsigned short* __restrict__ hi,
                  unsigned short* __restrict__ lo, int n4)
{
    int i = blockIdx.x * 256 + threadIdx.x;
    if (i >= n4) return;
    float4 v = ((const float4*)in)[i];
    ushort4 h, l;
    split1(v.x, h.x, l.x);
    split1(v.y, h.y, l.y);
    split1(v.z, h.z, l.z);
    split1(v.w, h.w, l.w);
    ((ushort4*)hi)[i] = h;
    ((ushort4*)lo)[i] = l;
}

// ---------------------------------------------------------------------------
// bf16x3 GEMM via mma.sync: D[8192][NN] = A[8192][1024] @ B[1024][NN]
// MODE 0: split fp32 acc -> qkvh/qkvl scatter.  MODE 1: fp32 write to Cout.
// ---------------------------------------------------------------------------
#define BK 32
#define NKB2 32
#define STAGES 3
#define ABUF 8192
#define BBUF 8192
#define STG_BYTES (2 * ABUF + 2 * BBUF)

template<int MODE, int NN>
__global__ __launch_bounds__(256)
void tc_gemm(const unsigned short* __restrict__ Ah, const unsigned short* __restrict__ Al,
             const unsigned short* __restrict__ Bh, const unsigned short* __restrict__ Bl,
             float* __restrict__ Cout)
{
    extern __shared__ __align__(1024) unsigned char gsm[];
    const uint32_t sbase = s2u(gsm);
    const int tid = threadIdx.x;
    const int lane = tid & 31, wid = tid >> 5;
    const int wm = wid & 3, wn = wid >> 2;
    const int bm = blockIdx.y * 128, bn = blockIdx.x * 128;

    const unsigned short* Abases[2] = { Ah + (size_t)bm * 1024, Al + (size_t)bm * 1024 };
    const unsigned short* Bbases[2] = { Bh + bn, Bl + bn };

    auto load_stage = [&](int st, int kb) {
        uint32_t sb = sbase + st * STG_BYTES;
#pragma unroll
        for (int sp = 0; sp < 2; sp++) {
#pragma unroll
            for (int i = 0; i < 2; i++) {
                int id = tid * 2 + i;
                int r = id >> 2, c = id & 3;
                cpa16(sb + sp * ABUF + SWA(r * 64 + c * 16),
                      Abases[sp] + (size_t)r * 1024 + kb * BK + c * 8);
                int rk = id >> 4, cc = id & 15;
                cpa16(sb + 2 * ABUF + sp * BBUF + SWB(rk * 256 + cc * 16),
                      Bbases[sp] + (size_t)(kb * BK + rk) * NN + cc * 8);
            }
        }
    };

    float acc[2][8][4];
#pragma unroll
    for (int mt = 0; mt < 2; mt++)
#pragma unroll
        for (int nt = 0; nt < 8; nt++)
#pragma unroll
            for (int q = 0; q < 4; q++) acc[mt][nt][q] = 0.f;

    load_stage(0, 0); cpa_commit();
    load_stage(1, 1); cpa_commit();

    const int a_lr = lane & 15;
    const int a_hk = (lane >> 4) << 4;

    for (int kb = 0; kb < NKB2; kb++) {
        const int cur = kb % STAGES;
        if (kb >= NKB2 - 2) cpa_wait<0>(); else cpa_wait<1>();
        __syncthreads();

        uint32_t sb = sbase + cur * STG_BYTES;
#pragma unroll
        for (int ks = 0; ks < 2; ks++) {
            uint32_t afr[2][2][4];
#pragma unroll
            for (int sp = 0; sp < 2; sp++)
#pragma unroll
                for (int mt = 0; mt < 2; mt++) {
                    int r = wm * 32 + mt * 16 + a_lr;
                    ldsm4(afr[sp][mt], sb + sp * ABUF + SWA(r * 64 + ks * 32 + a_hk));
                }
            uint32_t bfr[2][8][2];
#pragma unroll
            for (int sp = 0; sp < 2; sp++)
#pragma unroll
                for (int nt2 = 0; nt2 < 4; nt2++) {
                    int kk = ks * 16 + a_lr;
                    int nb = wn * 128 + nt2 * 32 + a_hk;
                    uint32_t t[4];
                    ldsm4t(t, sb + 2 * ABUF + sp * BBUF + SWB(kk * 256 + nb));
                    bfr[sp][nt2 * 2][0] = t[0]; bfr[sp][nt2 * 2][1] = t[1];
                    bfr[sp][nt2 * 2 + 1][0] = t[2]; bfr[sp][nt2 * 2 + 1][1] = t[3];
                }
#pragma unroll
            for (int mt = 0; mt < 2; mt++)
#pragma unroll
                for (int nt = 0; nt < 8; nt++) {
                    mma16816(acc[mt][nt], afr[0][mt], bfr[0][nt]);
                    mma16816(acc[mt][nt], afr[0][mt], bfr[1][nt]);
                    mma16816(acc[mt][nt], afr[1][mt], bfr[0][nt]);
                }
        }
        __syncthreads();
        if (kb + STAGES - 1 < NKB2) {
            load_stage((kb + STAGES - 1) % STAGES, kb + STAGES - 1);
            cpa_commit();
        }
    }

    const int gid = lane >> 2, tg = lane & 3;
#pragma unroll
    for (int mt = 0; mt < 2; mt++)
#pragma unroll
        for (int nt = 0; nt < 8; nt++) {
            int row0 = bm + wm * 32 + mt * 16 + gid;
            int col = bn + wn * 64 + nt * 8 + tg * 2;
#pragma unroll
            for (int half = 0; half < 2; half++) {
                int row = row0 + half * 8;
                float v0 = acc[mt][nt][half * 2], v1 = acc[mt][nt][half * 2 + 1];
                if (MODE == 0) {
                    int s = col >> 10, h = (col >> 6) & 15, d = col & 63;
                    int b = row >> 11, t = row & 2047;
                    size_t idx = (size_t)s * QKV_STRIDE +
                                 (((size_t)(b * Hn + h) * Tn + t) << 6) + d;
                    unsigned short h0, l0, h1, l1;
                    split1(v0, h0, l0);
                    split1(v1, h1, l1);
                    *(uint32_t*)&qkvh[idx] = (uint32_t)h0 | ((uint32_t)h1 << 16);
                    *(uint32_t*)&qkvl[idx] = (uint32_t)l0 | ((uint32_t)l1 << 16);
                } else {
                    *(float2*)&Cout[(size_t)row * NN + col] = make_float2(v0, v1);
                }
            }
        }
}

// ---------------------------------------------------------------------------
// Tensor-core flash attention (bf16x3 QK^T and PV, fp32 accum).
// 128 threads = 4 warps, each warp owns 16 q rows; block = 64 q rows of (b,h).
// ---------------------------------------------------------------------------
#define AQ_OFF 0            // Q hi 8KB
#define AQL_OFF 8192        // Q lo 8KB
#define AKV_OFF 16384       // 2 stages x (Kh,Kl,Vh,Vl) 8KB each
#define APOS_OFF (16384 + 65536)
#define ATTN_SMEM_SZ (16384 + 65536 + 512)

__global__ __launch_bounds__(128)
void attn_mma(const int* __restrict__ pos)
{
    extern __shared__ __align__(1024) unsigned char am[];
    const uint32_t sb = s2u(am);
    const int tid = threadIdx.x, lane = tid & 31, wm = tid >> 5;
    const int b = blockIdx.y >> 4, h = blockIdx.y & 15;
    const int i0 = blockIdx.x * 64;

    const size_t bh_off = ((size_t)(b * Hn + h) * Tn) << 6;
    const unsigned short* Qhg = qkvh + bh_off + ((size_t)i0 << 6);
    const unsigned short* Qlg = qkvl + bh_off + ((size_t)i0 << 6);
    const unsigned short* Khg = qkvh + (size_t)QKV_STRIDE + bh_off;
    const unsigned short* Klg = qkvl + (size_t)QKV_STRIDE + bh_off;
    const unsigned short* Vhg = qkvh + 2ull * QKV_STRIDE + bh_off;
    const unsigned short* Vlg = qkvl + 2ull * QKV_STRIDE + bh_off;
    const int* posb = pos + b * Tn;

    // Q tile -> smem (group 1)
#pragma unroll
    for (int i = 0; i < 4; i++) {
        int id = tid + i * 128;
        int r = id >> 3, c = id & 7;
        cpa16(sb + AQ_OFF + SW128(r * 128 + c * 16), Qhg + (size_t)r * 64 + c * 8);
        cpa16(sb + AQL_OFF + SW128(r * 128 + c * 16), Qlg + (size_t)r * 64 + c * 8);
    }
    cpa_commit();

    auto load_kv = [&](int st, int j0) {
        uint32_t base = sb + AKV_OFF + st * 32768;
        const unsigned short* srcs[4] = {
            Khg + ((size_t)j0 << 6), Klg + ((size_t)j0 << 6),
            Vhg + ((size_t)j0 << 6), Vlg + ((size_t)j0 << 6) };
#pragma unroll
        for (int buf = 0; buf < 4; buf++)
#pragma unroll
            for (int i = 0; i < 4; i++) {
                int id = tid + i * 128;
                int r = id >> 3, c = id & 7;
                cpa16(base + buf * 8192 + SW128(r * 128 + c * 16),
                      srcs[buf] + (size_t)r * 64 + c * 8);
            }
        if (tid < 16)
            cpa16(sb + APOS_OFF + st * 256 + tid * 16, posb + j0 + tid * 4);
    };

    load_kv(0, 0);
    cpa_commit();

    // Wait for Q (allow stage-0 group pending), build Q fragments once.
    cpa_wait<1>();
    __syncthreads();
    const int a_lr = lane & 15, a_hk = (lane >> 4) << 4;
    uint32_t qfh[4][4], qfl[4][4];
#pragma unroll
    for (int ks = 0; ks < 4; ks++) {
        int r = wm * 16 + a_lr;
        ldsm4(qfh[ks], sb + AQ_OFF + SW128(r * 128 + ks * 32 + a_hk));
        ldsm4(qfl[ks], sb + AQL_OFF + SW128(r * 128 + ks * 32 + a_hk));
    }

    const int pq0 = posb[i0 + wm * 16 + (lane >> 2)];
    const int pq1 = posb[i0 + wm * 16 + (lane >> 2) + 8];
    const int pqmax = posb[i0 + 63];
    const int jcol = 2 * (lane & 3);

    float m0 = -3e38f, m1 = -3e38f, l0 = 0.f, l1 = 0.f;
    float oacc[8][4];
#pragma unroll
    for (int nt = 0; nt < 8; nt++)
#pragma unroll
        for (int q = 0; q < 4; q++) oacc[nt][q] = 0.f;

    const float CS = 0.18033688011112042f;   // 0.125 * log2(e)

    int jb = 0, st = 0;
    for (;;) {
        int next = jb + 64;
        bool hn = (next < Tn) && (posb[next] <= pqmax);
        if (hn) { load_kv(st ^ 1, next); cpa_commit(); }
        if (hn) cpa_wait<1>(); else cpa_wait<0>();
        __syncthreads();

        const uint32_t kb_ = sb + AKV_OFF + st * 32768;
        const int* pkp = (const int*)(am + APOS_OFF + st * 256);

        // ---- S = Q K^T (bf16x3) ----
        float sacc[8][4];
#pragma unroll
        for (int nt = 0; nt < 8; nt++)
#pragma unroll
            for (int q = 0; q < 4; q++) sacc[nt][q] = 0.f;

#pragma unroll
        for (int ks = 0; ks < 4; ks++) {
            uint32_t kfh[4][4], kfl[4][4];
            const int g = lane >> 3;
            const int krow = (g >> 1) * 8 + (lane & 7);
            const int kchk = ks * 32 + (g & 1) * 16;
#pragma unroll
            for (int call = 0; call < 4; call++) {
                uint32_t off = SW128((call * 16 + krow) * 128 + kchk);
                ldsm4(kfh[call], kb_ + off);
                ldsm4(kfl[call], kb_ + 8192 + off);
            }
#pragma unroll
            for (int nt = 0; nt < 8; nt++) {
                const int c = nt >> 1, hf = (nt & 1) * 2;
                mma16816(sacc[nt], qfh[ks], &kfh[c][hf]);
                mma16816(sacc[nt], qfh[ks], &kfl[c][hf]);
                mma16816(sacc[nt], qfl[ks], &kfh[c][hf]);
            }
        }

        // ---- scale + mask + online softmax ----
        float mx0 = m0, mx1 = m1;
#pragma unroll
        for (int nt = 0; nt < 8; nt++) {
            int pk0 = pkp[nt * 8 + jcol], pk1 = pkp[nt * 8 + jcol + 1];
            float v0 = (pq0 < pk0) ? -3e38f : sacc[nt][0] * CS;
            float v1 = (pq0 < pk1) ? -3e38f : sacc[nt][1] * CS;
            float v2 = (pq1 < pk0) ? -3e38f : sacc[nt][2] * CS;
            float v3 = (pq1 < pk1) ? -3e38f : sacc[nt][3] * CS;
            sacc[nt][0] = v0; sacc[nt][1] = v1;
            sacc[nt][2] = v2; sacc[nt][3] = v3;
            mx0 = fmaxf(mx0, fmaxf(v0, v1));
            mx1 = fmaxf(mx1, fmaxf(v2, v3));
        }
        mx0 = fmaxf(mx0, __shfl_xor_sync(0xffffffffu, mx0, 1));
        mx0 = fmaxf(mx0, __shfl_xor_sync(0xffffffffu, mx0, 2));
        mx1 = fmaxf(mx1, __shfl_xor_sync(0xffffffffu, mx1, 1));
        mx1 = fmaxf(mx1, __shfl_xor_sync(0xffffffffu, mx1, 2));
        float al0 = exp2f(m0 - mx0), al1 = exp2f(m1 - mx1);
        m0 = mx0; m1 = mx1;

        float s0 = 0.f, s1 = 0.f;
#pragma unroll
        for (int nt = 0; nt < 8; nt++) {
            float p0 = exp2f(sacc[nt][0] - mx0);
            float p1 = exp2f(sacc[nt][1] - mx0);
            float p2 = exp2f(sacc[nt][2] - mx1);
            float p3 = exp2f(sacc[nt][3] - mx1);
            sacc[nt][0] = p0; sacc[nt][1] = p1;
            sacc[nt][2] = p2; sacc[nt][3] = p3;
            s0 += p0 + p1; s1 += p2 + p3;
        }
        s0 += __shfl_xor_sync(0xffffffffu, s0, 1);
        s0 += __shfl_xor_sync(0xffffffffu, s0, 2);
        s1 += __shfl_xor_sync(0xffffffffu, s1, 1);
        s1 += __shfl_xor_sync(0xffffffffu, s1, 2);
        l0 = l0 * al0 + s0;
        l1 = l1 * al1 + s1;
#pragma unroll
        for (int nt = 0; nt < 8; nt++) {
            oacc[nt][0] *= al0; oacc[nt][1] *= al0;
            oacc[nt][2] *= al1; oacc[nt][3] *= al1;
        }

        // ---- O += P V (bf16x3) ----
        const uint32_t vb = kb_ + 16384;
#pragma unroll
        for (int kt = 0; kt < 4; kt++) {
            uint32_t ph[4], pl[4];
#pragma unroll
            for (int q = 0; q < 4; q++) {
                const float* src = (q < 2) ? sacc[2 * kt] : sacc[2 * kt + 1];
                float a = src[(q & 1) * 2], c = src[(q & 1) * 2 + 1];
                uint32_t hp = pack_bf2(a, c);
                ph[q] = hp;
                float hl = __uint_as_float(hp << 16);
                float hh = __uint_as_float(hp & 0xFFFF0000u);
                pl[q] = pack_bf2(a - hl, c - hh);
            }
            uint32_t vfh[4][4], vfl[4][4];
#pragma unroll
            for (int call = 0; call < 4; call++) {
                uint32_t off = SW128((kt * 16 + a_lr) * 128 + call * 32 + a_hk);
                ldsm4t(vfh[call], vb + off);
                ldsm4t(vfl[call], vb + 8192 + off);
            }
#pragma unroll
            for (int nt = 0; nt < 8; nt++) {
                const int c = nt >> 1, hf = (nt & 1) * 2;
                mma16816(oacc[nt], ph, &vfh[c][hf]);
                mma16816(oacc[nt], ph, &vfl[c][hf]);
                mma16816(oacc[nt], pl, &vfh[c][hf]);
            }
        }

        __syncthreads();
        if (!hn) break;
        jb = next; st ^= 1;
    }

    // ---- epilogue: normalize, split to bf16 hi/lo, write [B][T][D] ----
    float inv0 = 1.f / l0, inv1 = 1.f / l1;
    int t0r = i0 + wm * 16 + (lane >> 2);
#pragma unroll
    for (int nt = 0; nt < 8; nt++) {
        int col = h * 64 + nt * 8 + jcol;
#pragma unroll
        for (int half = 0; half < 2; half++) {
            int t = t0r + half * 8;
            float inv = half ? inv1 : inv0;
            float v0 = oacc[nt][half * 2] * inv;
            float v1 = oacc[nt][half * 2 + 1] * inv;
            unsigned short h0, lw0, h1, lw1;
            split1(v0, h0, lw0);
            split1(v1, h1, lw1);
            size_t idx = ((size_t)b * Tn + t) * Dn + col;
            *(uint32_t*)&ga_hi[idx] = (uint32_t)h0 | ((uint32_t)h1 << 16);
            *(uint32_t*)&ga_lo[idx] = (uint32_t)lw0 | ((uint32_t)lw1 << 16);
        }
    }
}

// ---------------------------------------------------------------------------
extern "C" void kernel_launch(void* const* d_in, const int* in_sizes, int n_in,
                              void* d_out, int out_size)
{
    const float* x   = (const float*)d_in[0];
    const int*   pos = (const int*)d_in[1];
    const float* Wq  = (const float*)d_in[2];
    const float* Wo  = (const float*)d_in[3];
    float* out = (float*)d_out;

    unsigned short *p_xh, *p_xl, *p_wqh, *p_wql, *p_woh, *p_wol, *p_gah, *p_gal;
    cudaGetSymbolAddress((void**)&p_xh,  xa_hi);
    cudaGetSymbolAddress((void**)&p_xl,  xa_lo);
    cudaGetSymbolAddress((void**)&p_wqh, wq_hi);
    cudaGetSymbolAddress((void**)&p_wql, wq_lo);
    cudaGetSymbolAddress((void**)&p_woh, wo_hi);
    cudaGetSymbolAddress((void**)&p_wol, wo_lo);
    cudaGetSymbolAddress((void**)&p_gah, ga_hi);
    cudaGetSymbolAddress((void**)&p_gal, ga_lo);

    const int GEMM_SMEM = STAGES * STG_BYTES;   // 98304

    // 0) bf16 hi/lo splits
    int n4x = (Bn * Tn * Dn) / 4;
    split_kernel<<<(n4x + 255) / 256, 256>>>(x, p_xh, p_xl, n4x);
    int n4wq = (3 * Dn * Dn) / 4;
    split_kernel<<<(n4wq + 255) / 256, 256>>>(Wq, p_wqh, p_wql, n4wq);
    int n4wo = (Dn * Dn) / 4;
    split_kernel<<<(n4wo + 255) / 256, 256>>>(Wo, p_woh, p_wol, n4wo);

    // 1) QKV projection -> qkvh/qkvl (bf16 hi/lo, scattered)
    cudaFuncSetAttribute(tc_gemm<0, 3072>,
                         cudaFuncAttributeMaxDynamicSharedMemorySize, GEMM_SMEM);
    tc_gemm<0, 3072><<<dim3(24, 64), 256, GEMM_SMEM>>>(p_xh, p_xl, p_wqh, p_wql, nullptr);

    // 2) tensor-core flash attention -> ga_hi/ga_lo
    cudaFuncSetAttribute(attn_mma,
                         cudaFuncAttributeMaxDynamicSharedMemorySize, ATTN_SMEM_SZ);
    attn_mma<<<dim3(Tn / 64, Bn * Hn), 128, ATTN_SMEM_SZ>>>(pos);

    // 3) output projection -> d_out
    cudaFuncSetAttribute(tc_gemm<1, 1024>,
                         cudaFuncAttributeMaxDynamicSharedMemorySize, GEMM_SMEM);
    tc_gemm<1, 1024><<<dim3(8, 64), 256, GEMM_SMEM>>>(p_gah, p_gal, p_woh, p_wol, out);
}